// round 2
// baseline (speedup 1.0000x reference)
#include <cuda_runtime.h>

#define S_MAX 200000
#define N_MAX 250000
#define LB 64           // L == B == 64

// ---- device scratch (no allocations allowed) ----
__device__ float g_xT[(size_t)N_MAX * LB];    // x transposed [N,64]
__device__ float g_yT[(size_t)S_MAX * LB];    // y transposed [S,64]
__device__ float g_outT[(size_t)N_MAX * LB];  // out accumulator [N,64]
__device__ float g_z[LB * LB];                // z stored l-major: z[l][b]
__device__ int   g_cm[S_MAX];                 // # added new nodes per master
__device__ int   g_cnt[N_MAX];                // # masters mapping to n
__device__ float g_bdacc[N_MAX];              // segment sum of bd_m
__device__ unsigned char g_added[N_MAX];

// packed f32x2 helpers (SASS FFMA2 — only reachable via PTX)
#define FMA2(d, a, b) asm("fma.rn.f32x2 %0, %1, %2, %0;" : "+l"(d) : "l"(a), "l"(b))
#define PACKB(d, f)   asm("mov.b64 %0, {%1, %1};" : "=l"(d) : "f"(f))
#define UNPACK2(lo, hi, v) asm("mov.b64 {%0, %1}, %2;" : "=f"(lo), "=f"(hi) : "l"(v))

// ---------------- clear ----------------
__global__ void k_clear(int S, int N) {
    int i = blockIdx.x * blockDim.x + threadIdx.x;
    int tot4 = N * 16;  // N*64 floats / 4
    if (i < tot4) ((float4*)g_outT)[i] = make_float4(0.f, 0.f, 0.f, 0.f);
    if (i < N) { g_cnt[i] = 0; g_bdacc[i] = 0.f; }
    if (i < S) g_cm[i] = 0;
}

__global__ void k_zbias(const float* __restrict__ be) {
    int i = threadIdx.x + blockIdx.x * blockDim.x;
    if (i < LB * LB) g_z[i] = be[i >> 6];     // z[l][b] = be[l]
}

// ---------------- added flags + c_m ----------------
__global__ void k_added(const int* __restrict__ nn_n, const int* __restrict__ nn_m, int N) {
    int n = blockIdx.x * blockDim.x + threadIdx.x;
    if (n < N) {
        int m = nn_n[n];
        int a = (nn_m[m] != n) ? 1 : 0;
        g_added[n] = (unsigned char)a;
        if (a) atomicAdd(&g_cm[m], 1);
    }
}

// ---------------- cnt + bd segment sums ----------------
__global__ void k_mstats(const int* __restrict__ nn_m, const float* __restrict__ bd, int S) {
    int m = blockIdx.x * blockDim.x + threadIdx.x;
    if (m < S) {
        int nm = nn_m[m];
        atomicAdd(&g_cnt[nm], 1);
        atomicAdd(&g_bdacc[nm], bd[m]);
    }
}

// ---------------- x transpose [64,N] -> [N,64] ----------------
__global__ void k_xT(const float* __restrict__ x, int N) {
    __shared__ float tile[32][33];
    int n0 = blockIdx.x * 32;
    int b0 = blockIdx.y * 32;
    int tx = threadIdx.x, ty = threadIdx.y;   // 32 x 8
    #pragma unroll
    for (int i = 0; i < 32; i += 8) {
        int n = n0 + tx;
        tile[ty + i][tx] = (n < N) ? x[(size_t)(b0 + ty + i) * N + n] : 0.f;
    }
    __syncthreads();
    #pragma unroll
    for (int i = 0; i < 32; i += 8) {
        int n = n0 + ty + i;
        if (n < N) g_xT[(size_t)n * LB + b0 + tx] = tile[tx][ty + i];
    }
}

// ---------------- z GEMM: z[l][b] += sum over K=S+N rank-1 updates ----------------
// Packed f32x2: K-slices are paired; SMEM staged interleaved [g2][col*2 + sub]
// so one LDS.128 yields two (k0,k1)-packed f32x2 operands with zero mov overhead.
#define ZCHUNK 1024

__global__ void __launch_bounds__(256) k_z(const float* __restrict__ We,
                                           const int* __restrict__ nn_n,
                                           const int* __restrict__ nn_m,
                                           int S, int N) {
    __shared__ __align__(16) float sxf[4][128];
    __shared__ __align__(16) float swf[4][128];
    int tid = threadIdx.x;
    int tx = tid & 15, ty = tid >> 4;        // thread -> (l-group, b-group)
    int r = tid >> 5;                        // staging k-slice 0..7
    int c = (tid & 31) * 2;                  // staging col (2 floats)
    int g2 = r >> 1, sub = r & 1;

    unsigned long long acc[4][4];
    #pragma unroll
    for (int i = 0; i < 4; i++)
        #pragma unroll
        for (int j = 0; j < 4; j++) acc[i][j] = 0ULL;

    int Ktot = S + N;
    int k0 = blockIdx.x * ZCHUNK;

    for (int kk = 0; kk < ZCHUNK; kk += 8) {
        int k = k0 + kk + r;
        const float* px = 0;
        const float* pw = 0;
        float scale = 0.f;
        if (k < Ktot) {
            if (k < S) {
                scale = 1.0f / (float)(g_cm[k] + 1);
                pw = We + (size_t)k * 64;
                px = g_xT + (size_t)nn_m[k] * 64;
            } else {
                int n = k - S;
                if (g_added[n]) {
                    int m = nn_n[n];
                    scale = 1.0f / (float)(g_cm[m] + 1);
                    pw = We + (size_t)m * 64;
                    px = g_xT + (size_t)n * 64;
                }
            }
        }
        __syncthreads();
        if (pw) {
            float2 w2 = *(const float2*)(pw + c);
            float2 x2 = *(const float2*)(px + c);
            swf[g2][c * 2 + sub]     = w2.x * scale;
            swf[g2][c * 2 + 2 + sub] = w2.y * scale;
            sxf[g2][c * 2 + sub]     = x2.x;
            sxf[g2][c * 2 + 2 + sub] = x2.y;
        } else {
            swf[g2][c * 2 + sub] = 0.f;  swf[g2][c * 2 + 2 + sub] = 0.f;
            sxf[g2][c * 2 + sub] = 0.f;  sxf[g2][c * 2 + 2 + sub] = 0.f;
        }
        __syncthreads();
        #pragma unroll
        for (int g = 0; g < 4; g++) {
            ulonglong2 xa = *(const ulonglong2*)&sxf[g][ty * 8];
            ulonglong2 xb = *(const ulonglong2*)&sxf[g][ty * 8 + 4];
            ulonglong2 wa = *(const ulonglong2*)&swf[g][tx * 8];
            ulonglong2 wb = *(const ulonglong2*)&swf[g][tx * 8 + 4];
            unsigned long long xs[4] = {xa.x, xa.y, xb.x, xb.y};
            unsigned long long ws[4] = {wa.x, wa.y, wb.x, wb.y};
            #pragma unroll
            for (int i = 0; i < 4; i++)
                #pragma unroll
                for (int j = 0; j < 4; j++)
                    FMA2(acc[i][j], xs[i], ws[j]);
        }
    }
    #pragma unroll
    for (int i = 0; i < 4; i++)
        #pragma unroll
        for (int j = 0; j < 4; j++) {
            float lo, hi;
            UNPACK2(lo, hi, acc[i][j]);
            atomicAdd(&g_z[(tx * 4 + j) * 64 + (ty * 4 + i)], lo + hi);
        }
}

// ---------------- y = z @ Wd (per 128-column tile) + scatter into out_T ----------------
__global__ void __launch_bounds__(256) k_y1(const float* __restrict__ Wd,
                                            const int* __restrict__ nn_m, int S) {
    __shared__ __align__(16) float sbuf[128 * 68];   // first 4096: z[l][b]; reused as y tile
    int tid = threadIdx.x;
    int m0 = blockIdx.x * 128;
    for (int i = tid; i < 4096; i += 256) sbuf[i] = g_z[i];
    __syncthreads();

    int tx = tid & 31, ty = tid >> 5;
    int mbase = m0 + tx * 4;
    bool valid = (mbase + 4) <= S;

    unsigned long long accp[4][4];   // [b-pair][mj]
    #pragma unroll
    for (int p = 0; p < 4; p++)
        #pragma unroll
        for (int j = 0; j < 4; j++) accp[p][j] = 0ULL;

    #pragma unroll 4
    for (int l = 0; l < 64; l++) {
        float4 wv = valid ? *(const float4*)&Wd[(size_t)l * S + mbase]
                          : make_float4(0.f, 0.f, 0.f, 0.f);
        ulonglong2 zu0 = *(const ulonglong2*)&sbuf[l * 64 + ty * 8];
        ulonglong2 zu1 = *(const ulonglong2*)&sbuf[l * 64 + ty * 8 + 4];
        unsigned long long zp[4] = {zu0.x, zu0.y, zu1.x, zu1.y};
        unsigned long long wbk[4];
        PACKB(wbk[0], wv.x); PACKB(wbk[1], wv.y); PACKB(wbk[2], wv.z); PACKB(wbk[3], wv.w);
        #pragma unroll
        for (int p = 0; p < 4; p++)
            #pragma unroll
            for (int j = 0; j < 4; j++)
                FMA2(accp[p][j], zp[p], wbk[j]);
    }
    __syncthreads();  // done reading z region; reuse sbuf as y tile

    #pragma unroll
    for (int p = 0; p < 4; p++)
        #pragma unroll
        for (int j = 0; j < 4; j++) {
            float lo, hi;
            UNPACK2(lo, hi, accp[p][j]);
            sbuf[(tx * 4 + j) * 68 + (ty * 8 + p * 2)]     = lo;
            sbuf[(tx * 4 + j) * 68 + (ty * 8 + p * 2 + 1)] = hi;
        }
    __syncthreads();

    int cr = tid >> 4;              // 0..15
    int cc = (tid & 15) * 4;        // 0..60
    for (int rr = cr; rr < 128; rr += 16) {
        int m = m0 + rr;
        if (m < S) {
            float4 v = *(const float4*)&sbuf[rr * 68 + cc];
            *(float4*)&g_yT[(size_t)m * 64 + cc] = v;
            int nm = nn_m[m];
            float* dst = &g_outT[(size_t)nm * 64 + cc];
            atomicAdd(dst + 0, v.x);
            atomicAdd(dst + 1, v.y);
            atomicAdd(dst + 2, v.z);
            atomicAdd(dst + 3, v.w);
        }
    }
}

// ---------------- finalize: add gathered added-term, scale, bias, transpose-store ----------------
__global__ void __launch_bounds__(256) k_y2(float* __restrict__ out,
                                            const float* __restrict__ bd,
                                            const int* __restrict__ nn_n, int N) {
    __shared__ float t[64][65];
    int n0 = blockIdx.x * 64;
    int tid = threadIdx.x;
    int r = tid >> 2;
    int q = (tid & 3) * 16;
    int n = n0 + r;
    if (n < N) {
        int a = g_added[n];
        int m = nn_n[n];
        float dn = (float)(g_cnt[n] + a);
        if (dn < 1.f) dn = 1.f;
        float inv = 1.0f / dn;
        float bdn = (g_bdacc[n] + (a ? bd[m] : 0.f)) * inv;
        const float* yr = g_yT + (size_t)m * 64;
        const float* oa = g_outT + (size_t)n * 64;
        #pragma unroll
        for (int j = 0; j < 16; j += 4) {
            int b = q + j;
            float4 ov = *(const float4*)&oa[b];
            if (a) {
                float4 yv = *(const float4*)&yr[b];
                ov.x += yv.x; ov.y += yv.y; ov.z += yv.z; ov.w += yv.w;
            }
            t[r][b]     = ov.x * inv + bdn;
            t[r][b + 1] = ov.y * inv + bdn;
            t[r][b + 2] = ov.z * inv + bdn;
            t[r][b + 3] = ov.w * inv + bdn;
        }
    }
    __syncthreads();
    int cidx = tid & 63;
    if (n0 + cidx < N) {
        #pragma unroll
        for (int b = tid >> 6; b < 64; b += 4)
            out[(size_t)b * N + n0 + cidx] = t[cidx][b];
    }
}

extern "C" void kernel_launch(void* const* d_in, const int* in_sizes, int n_in,
                              void* d_out, int out_size) {
    const float* We   = (const float*)d_in[0];
    const float* be   = (const float*)d_in[1];
    const float* Wd   = (const float*)d_in[2];
    const float* bd   = (const float*)d_in[3];
    const float* x    = (const float*)d_in[4];
    const int*   nn_n = (const int*)d_in[5];
    const int*   nn_m = (const int*)d_in[6];
    int S = in_sizes[3];   // bd_m has S elements
    int N = in_sizes[5];   // nn_n has N elements
    float* out = (float*)d_out;

    int clearGrid = (N * 16 + 255) / 256;
    k_clear<<<clearGrid, 256>>>(S, N);
    k_zbias<<<16, 256>>>(be);
    k_added<<<(N + 255) / 256, 256>>>(nn_n, nn_m, N);
    k_mstats<<<(S + 255) / 256, 256>>>(nn_m, bd, S);

    dim3 tb(32, 8);
    dim3 tg((N + 31) / 32, 2);
    k_xT<<<tg, tb>>>(x, N);

    int Ktot = S + N;
    k_z<<<(Ktot + ZCHUNK - 1) / ZCHUNK, 256>>>(We, nn_n, nn_m, S, N);
    k_y1<<<(S + 127) / 128, 256>>>(Wd, nn_m, S);
    k_y2<<<(N + 63) / 64, 256>>>(out, bd, nn_n, N);
}

// round 3
// speedup vs baseline: 1.0905x; 1.0905x over previous
#include <cuda_runtime.h>

#define S_MAX 200000
#define N_MAX 250000
#define LB 64           // L == B == 64
#define ZCHUNK 1024

// ---- device scratch (no allocations allowed) ----
__device__ float g_xT[(size_t)N_MAX * LB];    // x transposed [N,64]
__device__ float g_yT[(size_t)S_MAX * LB];    // y transposed [S,64]
__device__ float g_z[LB * LB];                // z stored l-major: z[l][b]
__device__ int   g_cm[S_MAX];                 // # added new nodes per master
__device__ int   g_cnt[N_MAX];                // # masters mapping to n
__device__ float g_bdacc[N_MAX];              // segment sum of bd_m
__device__ unsigned char g_added[N_MAX];
// CSR of nn_m (inverse mapping n -> list of m)
__device__ int   g_off[N_MAX];
__device__ int   g_fill[N_MAX];
__device__ int   g_idx[S_MAX];
__device__ int   g_bsum[1024];
__device__ int   g_boff[1024];

// ---------------- clear (small arrays only — no 64MB outT anymore) ----------------
__global__ void k_clear(int S, int N) {
    int i = blockIdx.x * blockDim.x + threadIdx.x;
    if (i < N) { g_cnt[i] = 0; g_bdacc[i] = 0.f; g_fill[i] = 0; }
    if (i < S) g_cm[i] = 0;
}

__global__ void k_zbias(const float* __restrict__ be) {
    int i = threadIdx.x + blockIdx.x * blockDim.x;
    if (i < LB * LB) g_z[i] = be[i >> 6];     // z[l][b] = be[l]
}

// ---------------- added flags + c_m ----------------
__global__ void k_added(const int* __restrict__ nn_n, const int* __restrict__ nn_m, int N) {
    int n = blockIdx.x * blockDim.x + threadIdx.x;
    if (n < N) {
        int m = nn_n[n];
        int a = (nn_m[m] != n) ? 1 : 0;
        g_added[n] = (unsigned char)a;
        if (a) atomicAdd(&g_cm[m], 1);
    }
}

// ---------------- cnt + bd segment sums ----------------
__global__ void k_mstats(const int* __restrict__ nn_m, const float* __restrict__ bd, int S) {
    int m = blockIdx.x * blockDim.x + threadIdx.x;
    if (m < S) {
        int nm = nn_m[m];
        atomicAdd(&g_cnt[nm], 1);
        atomicAdd(&g_bdacc[nm], bd[m]);
    }
}

// ---------------- 2-level exclusive scan of g_cnt -> g_off ----------------
__global__ void k_scanA(int N) {
    __shared__ int sd[256];
    int t = threadIdx.x;
    int n = blockIdx.x * 256 + t;
    sd[t] = (n < N) ? g_cnt[n] : 0;
    __syncthreads();
    #pragma unroll
    for (int d = 128; d > 0; d >>= 1) {
        if (t < d) sd[t] += sd[t + d];
        __syncthreads();
    }
    if (t == 0) g_bsum[blockIdx.x] = sd[0];
}

__global__ void k_scanB(int nchunks) {
    __shared__ int sd[1024];
    int t = threadIdx.x;
    int v = (t < nchunks) ? g_bsum[t] : 0;
    sd[t] = v;
    __syncthreads();
    #pragma unroll
    for (int d = 1; d < 1024; d <<= 1) {
        int add = (t >= d) ? sd[t - d] : 0;
        __syncthreads();
        sd[t] += add;
        __syncthreads();
    }
    if (t < nchunks) g_boff[t] = sd[t] - v;   // exclusive
}

__global__ void k_scanC(int N) {
    __shared__ int sd[256];
    int t = threadIdx.x;
    int n = blockIdx.x * 256 + t;
    int v = (n < N) ? g_cnt[n] : 0;
    sd[t] = v;
    __syncthreads();
    #pragma unroll
    for (int d = 1; d < 256; d <<= 1) {
        int add = (t >= d) ? sd[t - d] : 0;
        __syncthreads();
        sd[t] += add;
        __syncthreads();
    }
    if (n < N) g_off[n] = g_boff[blockIdx.x] + sd[t] - v;  // exclusive
}

// ---------------- CSR index fill ----------------
__global__ void k_fill(const int* __restrict__ nn_m, int S) {
    int m = blockIdx.x * blockDim.x + threadIdx.x;
    if (m < S) {
        int nm = nn_m[m];
        int pos = g_off[nm] + atomicAdd(&g_fill[nm], 1);
        g_idx[pos] = m;
    }
}

// ---------------- x transpose [64,N] -> [N,64] ----------------
__global__ void k_xT(const float* __restrict__ x, int N) {
    __shared__ float tile[32][33];
    int n0 = blockIdx.x * 32;
    int b0 = blockIdx.y * 32;
    int tx = threadIdx.x, ty = threadIdx.y;   // 32 x 8
    #pragma unroll
    for (int i = 0; i < 32; i += 8) {
        int n = n0 + tx;
        tile[ty + i][tx] = (n < N) ? x[(size_t)(b0 + ty + i) * N + n] : 0.f;
    }
    __syncthreads();
    #pragma unroll
    for (int i = 0; i < 32; i += 8) {
        int n = n0 + ty + i;
        if (n < N) g_xT[(size_t)n * LB + b0 + tx] = tile[tx][ty + i];
    }
}

// ---------------- z GEMM: double-buffered staging, 1 barrier per 8-K step ----------------
__global__ void __launch_bounds__(256) k_z(const float* __restrict__ We,
                                           const int* __restrict__ nn_n,
                                           const int* __restrict__ nn_m,
                                           int S, int N) {
    __shared__ float sx[2][8][64];
    __shared__ float sw[2][8][64];
    int tid = threadIdx.x;
    int tx = tid & 15, ty = tid >> 4;        // thread -> (l-group, b-group)
    int r = tid >> 5;                        // staging k-slice 0..7
    int c = (tid & 31) * 2;                  // staging col (2 floats)
    float acc[4][4];
    #pragma unroll
    for (int i = 0; i < 4; i++)
        #pragma unroll
        for (int j = 0; j < 4; j++) acc[i][j] = 0.f;

    int Ktot = S + N;
    int k0 = blockIdx.x * ZCHUNK;

    // prefetch first 8-K slab into buffer 0
    {
        int k = k0 + r;
        const float* px = 0; const float* pw = 0; float scale = 0.f;
        if (k < Ktot) {
            if (k < S) {
                scale = 1.0f / (float)(g_cm[k] + 1);
                pw = We + (size_t)k * 64;
                px = g_xT + (size_t)nn_m[k] * 64;
            } else {
                int n = k - S;
                if (g_added[n]) {
                    int m = nn_n[n];
                    scale = 1.0f / (float)(g_cm[m] + 1);
                    pw = We + (size_t)m * 64;
                    px = g_xT + (size_t)n * 64;
                }
            }
        }
        float2 w2 = make_float2(0.f, 0.f), x2 = make_float2(0.f, 0.f);
        if (pw) {
            float2 a = *(const float2*)(pw + c);
            w2.x = a.x * scale; w2.y = a.y * scale;
            x2 = *(const float2*)(px + c);
        }
        sw[0][r][c] = w2.x; sw[0][r][c + 1] = w2.y;
        sx[0][r][c] = x2.x; sx[0][r][c + 1] = x2.y;
    }
    __syncthreads();

    int cur = 0;
    for (int kk = 8; kk <= ZCHUNK; kk += 8) {
        // issue next slab's gathers first (latency overlapped by compute below)
        float2 nw = make_float2(0.f, 0.f), nx = make_float2(0.f, 0.f);
        if (kk < ZCHUNK) {
            int k = k0 + kk + r;
            const float* px = 0; const float* pw = 0; float scale = 0.f;
            if (k < Ktot) {
                if (k < S) {
                    scale = 1.0f / (float)(g_cm[k] + 1);
                    pw = We + (size_t)k * 64;
                    px = g_xT + (size_t)nn_m[k] * 64;
                } else {
                    int n = k - S;
                    if (g_added[n]) {
                        int m = nn_n[n];
                        scale = 1.0f / (float)(g_cm[m] + 1);
                        pw = We + (size_t)m * 64;
                        px = g_xT + (size_t)n * 64;
                    }
                }
            }
            if (pw) {
                float2 a = *(const float2*)(pw + c);
                nw.x = a.x * scale; nw.y = a.y * scale;
                nx = *(const float2*)(px + c);
            }
        }
        // compute on current buffer
        #pragma unroll
        for (int g = 0; g < 8; g++) {
            float4 xv = *(const float4*)&sx[cur][g][ty * 4];
            float4 wv = *(const float4*)&sw[cur][g][tx * 4];
            acc[0][0] += xv.x * wv.x; acc[0][1] += xv.x * wv.y; acc[0][2] += xv.x * wv.z; acc[0][3] += xv.x * wv.w;
            acc[1][0] += xv.y * wv.x; acc[1][1] += xv.y * wv.y; acc[1][2] += xv.y * wv.z; acc[1][3] += xv.y * wv.w;
            acc[2][0] += xv.z * wv.x; acc[2][1] += xv.z * wv.y; acc[2][2] += xv.z * wv.z; acc[2][3] += xv.z * wv.w;
            acc[3][0] += xv.w * wv.x; acc[3][1] += xv.w * wv.y; acc[3][2] += xv.w * wv.z; acc[3][3] += xv.w * wv.w;
        }
        // store next slab into the other buffer (nobody reads it this iter)
        if (kk < ZCHUNK) {
            sw[cur ^ 1][r][c] = nw.x; sw[cur ^ 1][r][c + 1] = nw.y;
            sx[cur ^ 1][r][c] = nx.x; sx[cur ^ 1][r][c + 1] = nx.y;
        }
        __syncthreads();
        cur ^= 1;
    }

    #pragma unroll
    for (int i = 0; i < 4; i++)
        #pragma unroll
        for (int j = 0; j < 4; j++)
            atomicAdd(&g_z[(tx * 4 + j) * 64 + (ty * 4 + i)], acc[i][j]);
}

// ---------------- y = z @ Wd (per 128-column tile), store yT only ----------------
__global__ void __launch_bounds__(256) k_y1(const float* __restrict__ Wd, int S) {
    __shared__ float sbuf[128 * 68];   // first 4096 floats: z[l][b]; reused as y tile [128][68]
    int tid = threadIdx.x;
    int m0 = blockIdx.x * 128;
    for (int i = tid; i < 4096; i += 256) sbuf[i] = g_z[i];
    __syncthreads();

    int tx = tid & 31, ty = tid >> 5;
    int mbase = m0 + tx * 4;
    bool valid = (mbase + 4) <= S;

    float acc[8][4];
    #pragma unroll
    for (int bi = 0; bi < 8; bi++)
        #pragma unroll
        for (int mj = 0; mj < 4; mj++) acc[bi][mj] = 0.f;

    #pragma unroll 4
    for (int l = 0; l < 64; l++) {
        float4 wv = valid ? *(const float4*)&Wd[(size_t)l * S + mbase]
                          : make_float4(0.f, 0.f, 0.f, 0.f);
        float4 z0 = *(const float4*)&sbuf[l * 64 + ty * 8];
        float4 z1 = *(const float4*)&sbuf[l * 64 + ty * 8 + 4];
        float zb[8] = {z0.x, z0.y, z0.z, z0.w, z1.x, z1.y, z1.z, z1.w};
        #pragma unroll
        for (int bi = 0; bi < 8; bi++) {
            acc[bi][0] += zb[bi] * wv.x;
            acc[bi][1] += zb[bi] * wv.y;
            acc[bi][2] += zb[bi] * wv.z;
            acc[bi][3] += zb[bi] * wv.w;
        }
    }
    __syncthreads();  // done reading z region; reuse sbuf as y tile

    #pragma unroll
    for (int bi = 0; bi < 8; bi++)
        #pragma unroll
        for (int mj = 0; mj < 4; mj++)
            sbuf[(tx * 4 + mj) * 68 + (ty * 8 + bi)] = acc[bi][mj];
    __syncthreads();

    int cr = tid >> 4;              // 0..15
    int cc = (tid & 15) * 4;        // 0..60
    for (int rr = cr; rr < 128; rr += 16) {
        int m = m0 + rr;
        if (m < S)
            *(float4*)&g_yT[(size_t)m * 64 + cc] = *(const float4*)&sbuf[rr * 68 + cc];
    }
}

// ---------------- finalize: CSR gather of y rows, scale, bias, transpose-store ----------------
__global__ void __launch_bounds__(256) k_y2(float* __restrict__ out,
                                            const float* __restrict__ bd,
                                            const int* __restrict__ nn_n, int N) {
    __shared__ float t[64][65];
    int n0 = blockIdx.x * 64;
    int tid = threadIdx.x;
    int r = tid >> 2;               // n within tile 0..63
    int q = (tid & 3) * 16;         // 16 b-columns per thread
    int n = n0 + r;
    if (n < N) {
        int a = g_added[n];
        int mstar = nn_n[n];
        int cnt = g_cnt[n];
        float dn = (float)(cnt + a);
        if (dn < 1.f) dn = 1.f;
        float inv = 1.0f / dn;
        float bdn = (g_bdacc[n] + (a ? bd[mstar] : 0.f)) * inv;

        float acc[16];
        #pragma unroll
        for (int j = 0; j < 16; j++) acc[j] = 0.f;

        int o = g_off[n];
        for (int s = 0; s < cnt; s++) {
            int m = g_idx[o + s];
            const float* yr = g_yT + (size_t)m * 64 + q;
            #pragma unroll
            for (int j = 0; j < 16; j += 4) {
                float4 v = *(const float4*)(yr + j);
                acc[j] += v.x; acc[j + 1] += v.y; acc[j + 2] += v.z; acc[j + 3] += v.w;
            }
        }
        if (a) {
            const float* yr = g_yT + (size_t)mstar * 64 + q;
            #pragma unroll
            for (int j = 0; j < 16; j += 4) {
                float4 v = *(const float4*)(yr + j);
                acc[j] += v.x; acc[j + 1] += v.y; acc[j + 2] += v.z; acc[j + 3] += v.w;
            }
        }
        #pragma unroll
        for (int j = 0; j < 16; j++) t[r][q + j] = acc[j] * inv + bdn;
    }
    __syncthreads();
    int cidx = tid & 63;
    if (n0 + cidx < N) {
        #pragma unroll
        for (int b = tid >> 6; b < 64; b += 4)
            out[(size_t)b * N + n0 + cidx] = t[cidx][b];
    }
}

extern "C" void kernel_launch(void* const* d_in, const int* in_sizes, int n_in,
                              void* d_out, int out_size) {
    const float* We   = (const float*)d_in[0];
    const float* be   = (const float*)d_in[1];
    const float* Wd   = (const float*)d_in[2];
    const float* bd   = (const float*)d_in[3];
    const float* x    = (const float*)d_in[4];
    const int*   nn_n = (const int*)d_in[5];
    const int*   nn_m = (const int*)d_in[6];
    int S = in_sizes[3];   // bd_m has S elements
    int N = in_sizes[5];   // nn_n has N elements
    float* out = (float*)d_out;

    int mx = (N > S) ? N : S;
    k_clear<<<(mx + 255) / 256, 256>>>(S, N);
    k_zbias<<<16, 256>>>(be);
    k_added<<<(N + 255) / 256, 256>>>(nn_n, nn_m, N);
    k_mstats<<<(S + 255) / 256, 256>>>(nn_m, bd, S);

    int nchunks = (N + 255) / 256;
    k_scanA<<<nchunks, 256>>>(N);
    k_scanB<<<1, 1024>>>(nchunks);
    k_scanC<<<nchunks, 256>>>(N);
    k_fill<<<(S + 255) / 256, 256>>>(nn_m, S);

    dim3 tb(32, 8);
    dim3 tg((N + 31) / 32, 2);
    k_xT<<<tg, tb>>>(x, N);

    int Ktot = S + N;
    k_z<<<(Ktot + ZCHUNK - 1) / ZCHUNK, 256>>>(We, nn_n, nn_m, S, N);
    k_y1<<<(S + 127) / 128, 256>>>(Wd, S);
    k_y2<<<(N + 63) / 64, 256>>>(out, bd, nn_n, N);
}

// round 4
// speedup vs baseline: 1.4455x; 1.3256x over previous
#include <cuda_runtime.h>

#define S_MAX 200000
#define N_MAX 250000
#define LB 64           // L == B == 64
#define ZCHUNK 512

// ---- device scratch (no allocations allowed) ----
__device__ float g_xT[(size_t)N_MAX * LB];    // x transposed [N,64]
__device__ float g_xagg[(size_t)S_MAX * LB];  // aggregated+scaled x per master [S,64]
__device__ float g_yT[(size_t)S_MAX * LB];    // y transposed [S,64]
__device__ float g_z[LB * LB];                // z stored l-major: z[l][b]
__device__ int   g_cm[S_MAX];                 // # added new nodes per master
__device__ int   g_cnt[N_MAX];                // # masters mapping to n
__device__ float g_bdacc[N_MAX];              // segment sum of bd_m
__device__ unsigned char g_added[N_MAX];
// CSR A: master m -> added new nodes n (offsets over S, indices size N)
__device__ int   g_offA[S_MAX];
__device__ int   g_fillA[S_MAX];
__device__ int   g_idxA[N_MAX];
// CSR Y: new node n -> masters m (offsets over N, indices size S)
__device__ int   g_offY[N_MAX];
__device__ int   g_fillY[N_MAX];
__device__ int   g_idxY[S_MAX];
// scan temporaries (two chains)
__device__ int   g_bsumA[1024];
__device__ int   g_boffA[1024];
__device__ int   g_bsumB[1024];
__device__ int   g_boffB[1024];

// ---------------- prep: clear everything + z bias ----------------
__global__ void k_prep(const float* __restrict__ be, int S, int N) {
    int i = blockIdx.x * blockDim.x + threadIdx.x;
    if (i < S) { g_cm[i] = 0; g_fillA[i] = 0; }
    if (i < N) { g_cnt[i] = 0; g_bdacc[i] = 0.f; g_fillY[i] = 0; }
    if (i < LB * LB) g_z[i] = be[i >> 6];     // z[l][b] = be[l]
}

// ---------------- stats: added flags + c_m + cnt + bdacc ----------------
__global__ void k_stats(const int* __restrict__ nn_n, const int* __restrict__ nn_m,
                        const float* __restrict__ bd, int S, int N) {
    int i = blockIdx.x * blockDim.x + threadIdx.x;
    if (i < N) {
        int m = nn_n[i];
        int a = (nn_m[m] != i) ? 1 : 0;
        g_added[i] = (unsigned char)a;
        if (a) atomicAdd(&g_cm[m], 1);
    }
    if (i < S) {
        int nm = nn_m[i];
        atomicAdd(&g_cnt[nm], 1);
        atomicAdd(&g_bdacc[nm], bd[i]);
    }
}

// ---------------- x transpose [64,N] -> [N,64] ----------------
__global__ void k_xT(const float* __restrict__ x, int N) {
    __shared__ float tile[32][33];
    int n0 = blockIdx.x * 32;
    int b0 = blockIdx.y * 32;
    int tx = threadIdx.x, ty = threadIdx.y;   // 32 x 8
    #pragma unroll
    for (int i = 0; i < 32; i += 8) {
        int n = n0 + tx;
        tile[ty + i][tx] = (n < N) ? x[(size_t)(b0 + ty + i) * N + n] : 0.f;
    }
    __syncthreads();
    #pragma unroll
    for (int i = 0; i < 32; i += 8) {
        int n = n0 + ty + i;
        if (n < N) g_xT[(size_t)n * LB + b0 + tx] = tile[tx][ty + i];
    }
}

// ---------------- dual 2-level exclusive scans: cm (S) and cnt (N) ----------------
__global__ void k_scan1(int S, int N, int cA) {
    __shared__ int sd[256];
    int t = threadIdx.x;
    int blk = blockIdx.x;
    const int* src; int len; int cbase;
    if (blk < cA) { src = g_cm; len = S; cbase = blk; }
    else          { src = g_cnt; len = N; cbase = blk - cA; }
    int n = cbase * 256 + t;
    sd[t] = (n < len) ? src[n] : 0;
    __syncthreads();
    #pragma unroll
    for (int d = 128; d > 0; d >>= 1) {
        if (t < d) sd[t] += sd[t + d];
        __syncthreads();
    }
    if (t == 0) {
        if (blk < cA) g_bsumA[cbase] = sd[0];
        else          g_bsumB[cbase] = sd[0];
    }
}

__global__ void k_scan2(int cA, int cB) {
    __shared__ int sd[1024];
    int t = threadIdx.x;
    const int* in  = (blockIdx.x == 0) ? g_bsumA : g_bsumB;
    int*       outp = (blockIdx.x == 0) ? g_boffA : g_boffB;
    int nch = (blockIdx.x == 0) ? cA : cB;
    int v = (t < nch) ? in[t] : 0;
    sd[t] = v;
    __syncthreads();
    #pragma unroll
    for (int d = 1; d < 1024; d <<= 1) {
        int add = (t >= d) ? sd[t - d] : 0;
        __syncthreads();
        sd[t] += add;
        __syncthreads();
    }
    if (t < nch) outp[t] = sd[t] - v;   // exclusive
}

__global__ void k_scan3(int S, int N, int cA) {
    __shared__ int sd[256];
    int t = threadIdx.x;
    int blk = blockIdx.x;
    const int* src; int len; int cbase; const int* boff; int* dst;
    if (blk < cA) { src = g_cm;  len = S; cbase = blk;      boff = g_boffA; dst = g_offA; }
    else          { src = g_cnt; len = N; cbase = blk - cA; boff = g_boffB; dst = g_offY; }
    int n = cbase * 256 + t;
    int v = (n < len) ? src[n] : 0;
    sd[t] = v;
    __syncthreads();
    #pragma unroll
    for (int d = 1; d < 256; d <<= 1) {
        int add = (t >= d) ? sd[t - d] : 0;
        __syncthreads();
        sd[t] += add;
        __syncthreads();
    }
    if (n < len) dst[n] = boff[cbase] + sd[t] - v;  // exclusive
}

// ---------------- CSR index fills (both) ----------------
__global__ void k_fill(const int* __restrict__ nn_n, const int* __restrict__ nn_m,
                       int S, int N) {
    int i = blockIdx.x * blockDim.x + threadIdx.x;
    if (i < N && g_added[i]) {
        int m = nn_n[i];
        int pos = g_offA[m] + atomicAdd(&g_fillA[m], 1);
        g_idxA[pos] = i;
    }
    if (i < S) {
        int nm = nn_m[i];
        int pos = g_offY[nm] + atomicAdd(&g_fillY[nm], 1);
        g_idxY[pos] = i;
    }
}

// ---------------- Xagg[m] = scale[m] * ( xT[nn_m[m]] + sum added rows ) ----------------
__global__ void __launch_bounds__(256) k_xagg(const int* __restrict__ nn_m, int S) {
    int w = (blockIdx.x * blockDim.x + threadIdx.x) >> 5;
    int lane = threadIdx.x & 31;
    if (w >= S) return;
    int cm = g_cm[w];
    float scale = 1.0f / (float)(cm + 1);
    const float* base = g_xT + (size_t)nn_m[w] * 64 + lane * 2;
    float2 acc = *(const float2*)base;
    int o = g_offA[w];
    for (int s = 0; s < cm; s++) {
        int n = g_idxA[o + s];
        float2 v = *(const float2*)(g_xT + (size_t)n * 64 + lane * 2);
        acc.x += v.x; acc.y += v.y;
    }
    acc.x *= scale; acc.y *= scale;
    *(float2*)(g_xagg + (size_t)w * 64 + lane * 2) = acc;
}

// ---------------- z GEMM: pure streaming, z = We^T @ Xagg over K=S ----------------
__global__ void __launch_bounds__(256) k_z(const float* __restrict__ We, int S) {
    __shared__ float sx[2][16][64];
    __shared__ float sw[2][16][64];
    int tid = threadIdx.x;
    int tx = tid & 15, ty = tid >> 4;        // compute mapping: l-group, b-group
    int row = tid >> 4;                      // staging row 0..15
    int col4 = (tid & 15) * 4;               // staging col (float4)
    float acc[4][4];
    #pragma unroll
    for (int i = 0; i < 4; i++)
        #pragma unroll
        for (int j = 0; j < 4; j++) acc[i][j] = 0.f;

    int k0 = blockIdx.x * ZCHUNK;

    // prefetch slab 0
    {
        int k = k0 + row;
        float4 w4 = make_float4(0.f,0.f,0.f,0.f), x4 = make_float4(0.f,0.f,0.f,0.f);
        if (k < S) {
            w4 = *(const float4*)&We[(size_t)k * 64 + col4];
            x4 = *(const float4*)&g_xagg[(size_t)k * 64 + col4];
        }
        *(float4*)&sw[0][row][col4] = w4;
        *(float4*)&sx[0][row][col4] = x4;
    }
    __syncthreads();

    int cur = 0;
    for (int kk = 16; kk <= ZCHUNK; kk += 16) {
        float4 nw = make_float4(0.f,0.f,0.f,0.f), nx = make_float4(0.f,0.f,0.f,0.f);
        if (kk < ZCHUNK) {
            int k = k0 + kk + row;
            if (k < S) {
                nw = *(const float4*)&We[(size_t)k * 64 + col4];
                nx = *(const float4*)&g_xagg[(size_t)k * 64 + col4];
            }
        }
        #pragma unroll
        for (int g = 0; g < 16; g++) {
            float4 xv = *(const float4*)&sx[cur][g][ty * 4];
            float4 wv = *(const float4*)&sw[cur][g][tx * 4];
            acc[0][0] += xv.x * wv.x; acc[0][1] += xv.x * wv.y; acc[0][2] += xv.x * wv.z; acc[0][3] += xv.x * wv.w;
            acc[1][0] += xv.y * wv.x; acc[1][1] += xv.y * wv.y; acc[1][2] += xv.y * wv.z; acc[1][3] += xv.y * wv.w;
            acc[2][0] += xv.z * wv.x; acc[2][1] += xv.z * wv.y; acc[2][2] += xv.z * wv.z; acc[2][3] += xv.z * wv.w;
            acc[3][0] += xv.w * wv.x; acc[3][1] += xv.w * wv.y; acc[3][2] += xv.w * wv.z; acc[3][3] += xv.w * wv.w;
        }
        if (kk < ZCHUNK) {
            *(float4*)&sw[cur ^ 1][row][col4] = nw;
            *(float4*)&sx[cur ^ 1][row][col4] = nx;
        }
        __syncthreads();
        cur ^= 1;
    }

    #pragma unroll
    for (int i = 0; i < 4; i++)
        #pragma unroll
        for (int j = 0; j < 4; j++)
            atomicAdd(&g_z[(tx * 4 + j) * 64 + (ty * 4 + i)], acc[i][j]);
}

// ---------------- y = z @ Wd (per 128-column tile), store yT ----------------
__global__ void __launch_bounds__(256) k_y1(const float* __restrict__ Wd, int S) {
    __shared__ float sbuf[128 * 68];   // first 4096 floats: z[l][b]; reused as y tile [128][68]
    int tid = threadIdx.x;
    int m0 = blockIdx.x * 128;
    for (int i = tid; i < 4096; i += 256) sbuf[i] = g_z[i];
    __syncthreads();

    int tx = tid & 31, ty = tid >> 5;
    int mbase = m0 + tx * 4;
    bool valid = (mbase + 4) <= S;

    float acc[8][4];
    #pragma unroll
    for (int bi = 0; bi < 8; bi++)
        #pragma unroll
        for (int mj = 0; mj < 4; mj++) acc[bi][mj] = 0.f;

    #pragma unroll 4
    for (int l = 0; l < 64; l++) {
        float4 wv = valid ? *(const float4*)&Wd[(size_t)l * S + mbase]
                          : make_float4(0.f, 0.f, 0.f, 0.f);
        float4 z0 = *(const float4*)&sbuf[l * 64 + ty * 8];
        float4 z1 = *(const float4*)&sbuf[l * 64 + ty * 8 + 4];
        float zb[8] = {z0.x, z0.y, z0.z, z0.w, z1.x, z1.y, z1.z, z1.w};
        #pragma unroll
        for (int bi = 0; bi < 8; bi++) {
            acc[bi][0] += zb[bi] * wv.x;
            acc[bi][1] += zb[bi] * wv.y;
            acc[bi][2] += zb[bi] * wv.z;
            acc[bi][3] += zb[bi] * wv.w;
        }
    }
    __syncthreads();

    #pragma unroll
    for (int bi = 0; bi < 8; bi++)
        #pragma unroll
        for (int mj = 0; mj < 4; mj++)
            sbuf[(tx * 4 + mj) * 68 + (ty * 8 + bi)] = acc[bi][mj];
    __syncthreads();

    int cr = tid >> 4;              // 0..15
    int cc = (tid & 15) * 4;        // 0..60
    for (int rr = cr; rr < 128; rr += 16) {
        int m = m0 + rr;
        if (m < S)
            *(float4*)&g_yT[(size_t)m * 64 + cc] = *(const float4*)&sbuf[rr * 68 + cc];
    }
}

// ---------------- finalize: CSR gather, scale, bias, transpose-store ----------------
__global__ void __launch_bounds__(256) k_y2(float* __restrict__ out,
                                            const float* __restrict__ bd,
                                            const int* __restrict__ nn_n, int N) {
    __shared__ float t[64][65];
    int n0 = blockIdx.x * 64;
    int tid = threadIdx.x;
    int r = tid >> 2;               // n within tile 0..63
    int q = (tid & 3) * 16;         // 16 b-columns per thread
    int n = n0 + r;
    if (n < N) {
        int a = g_added[n];
        int mstar = nn_n[n];
        int cnt = g_cnt[n];
        float dn = (float)(cnt + a);
        if (dn < 1.f) dn = 1.f;
        float inv = 1.0f / dn;
        float bdn = (g_bdacc[n] + (a ? bd[mstar] : 0.f)) * inv;

        float acc[16];
        #pragma unroll
        for (int j = 0; j < 16; j++) acc[j] = 0.f;

        int o = g_offY[n];
        for (int s = 0; s < cnt; s++) {
            int m = g_idxY[o + s];
            const float* yr = g_yT + (size_t)m * 64 + q;
            #pragma unroll
            for (int j = 0; j < 16; j += 4) {
                float4 v = *(const float4*)(yr + j);
                acc[j] += v.x; acc[j + 1] += v.y; acc[j + 2] += v.z; acc[j + 3] += v.w;
            }
        }
        if (a) {
            const float* yr = g_yT + (size_t)mstar * 64 + q;
            #pragma unroll
            for (int j = 0; j < 16; j += 4) {
                float4 v = *(const float4*)(yr + j);
                acc[j] += v.x; acc[j + 1] += v.y; acc[j + 2] += v.z; acc[j + 3] += v.w;
            }
        }
        #pragma unroll
        for (int j = 0; j < 16; j++) t[r][q + j] = acc[j] * inv + bdn;
    }
    __syncthreads();
    int cidx = tid & 63;
    if (n0 + cidx < N) {
        #pragma unroll
        for (int b = tid >> 6; b < 64; b += 4)
            out[(size_t)b * N + n0 + cidx] = t[cidx][b];
    }
}

extern "C" void kernel_launch(void* const* d_in, const int* in_sizes, int n_in,
                              void* d_out, int out_size) {
    const float* We   = (const float*)d_in[0];
    const float* be   = (const float*)d_in[1];
    const float* Wd   = (const float*)d_in[2];
    const float* bd   = (const float*)d_in[3];
    const float* x    = (const float*)d_in[4];
    const int*   nn_n = (const int*)d_in[5];
    const int*   nn_m = (const int*)d_in[6];
    int S = in_sizes[3];   // bd_m has S elements
    int N = in_sizes[5];   // nn_n has N elements
    float* out = (float*)d_out;

    int mx = (N > S) ? N : S;
    int cA = (S + 255) / 256;     // chunks over S (cm scan)
    int cB = (N + 255) / 256;     // chunks over N (cnt scan)

    k_prep<<<(mx + 255) / 256, 256>>>(be, S, N);
    k_stats<<<(mx + 255) / 256, 256>>>(nn_n, nn_m, bd, S, N);

    dim3 tb(32, 8);
    dim3 tg((N + 31) / 32, 2);
    k_xT<<<tg, tb>>>(x, N);

    k_scan1<<<cA + cB, 256>>>(S, N, cA);
    k_scan2<<<2, 1024>>>(cA, cB);
    k_scan3<<<cA + cB, 256>>>(S, N, cA);
    k_fill<<<(mx + 255) / 256, 256>>>(nn_n, nn_m, S, N);

    k_xagg<<<(S * 32 + 255) / 256, 256>>>(nn_m, S);
    k_z<<<(S + ZCHUNK - 1) / ZCHUNK, 256>>>(We, S);
    k_y1<<<(S + 127) / 128, 256>>>(Wd, S);
    k_y2<<<(N + 63) / 64, 256>>>(out, bd, nn_n, N);
}